// round 7
// baseline (speedup 1.0000x reference)
#include <cuda_runtime.h>
#include <math.h>

#define NB 16
#define CH 3
#define HGT 512
#define WID 512
#define HW (HGT*WID)          // 262144

#define TILE_H 16
#define NTHR   256            // 2 columns per thread -> full 512-wide rows
#define NBLOCKS (NB * (HGT / TILE_H))   // 512

// Per-image accumulators + completion counter. Zero-initialized at load;
// the last block resets everything so each graph replay starts clean.
__device__ double   g_S[NB];
__device__ double   g_SS[NB];
__device__ double   g_WR[NB];
__device__ unsigned g_done;

__device__ __forceinline__ int reflect_idx(int i, int n) {
    if (i < 0)  return -i;
    if (i >= n) return 2*n - 2 - i;
    return i;
}

// ---------------------------------------------------------------------------
// Fully fused: residual on-the-fly + 7x7 local unbiased variance (reflect)
// + per-image S/SS/WR accumulation + final loss (last block).
// Block: 256 threads, thread t owns columns {2t, 2t+1} (float2 loads).
// Tile: full 512-wide x 16 rows. Grid: (1, 32, 16) = 512 blocks.
// Vertical 7-window: register ring with INCREMENTAL running sums.
// Horizontal 7-tap: smem stage, x-reflect free.
// ---------------------------------------------------------------------------
__global__ __launch_bounds__(NTHR, 5) void fused_kernel(
    const float* __restrict__ pred, const float* __restrict__ targ,
    float* __restrict__ out)
{
    const int n   = blockIdx.z;
    const int by  = blockIdx.y * TILE_H;
    const int tid = threadIdx.x;
    const int c0  = 2 * tid;

    __shared__ float2 sV[4][WID];        // vertical (sum, sumsq) per column
    __shared__ float  red[3][8];
    __shared__ int    sLast;

    const float* __restrict__ p0 = pred + (size_t)n * CH * HW;
    const float* __restrict__ t0 = targ + (size_t)n * CH * HW;

    float2 ring[7];                      // .x col c0, .y col c0+1
    float2 centerR[4];
    float s_acc = 0.f, ss_acc = 0.f, wr_acc = 0.f;
    // running sums over ring[1..6] (the 6 rows preceding the incoming one)
    float sx_run = 0.f, qx_run = 0.f, sy_run = 0.f, qy_run = 0.f;

    // Prefill ring slots 1..6 with logical rows by-3 .. by+2.
    #pragma unroll
    for (int k = 0; k < 6; ++k) {
        const int yr = by - 3 + k;
        const int gy = reflect_idx(yr, HGT);
        const int idx = gy * WID + c0;
        float2 pa = *(const float2*)(p0 + idx);
        float2 ta = *(const float2*)(t0 + idx);
        float2 pb = *(const float2*)(p0 + HW + idx);
        float2 tb = *(const float2*)(t0 + HW + idx);
        float2 pc = *(const float2*)(p0 + 2*HW + idx);
        float2 tc = *(const float2*)(t0 + 2*HW + idx);
        float rx = fabsf(pa.x - ta.x) + fabsf(pb.x - tb.x) + fabsf(pc.x - tc.x);
        float ry = fabsf(pa.y - ta.y) + fabsf(pb.y - tb.y) + fabsf(pc.y - tc.y);
        ring[k + 1] = make_float2(rx, ry);
        sx_run += rx; qx_run += rx * rx;
        sy_run += ry; qy_run += ry * ry;
        if (k >= 3) {                     // rows by..by+2: count once
            s_acc  += rx + ry;
            ss_acc += rx*rx + ry*ry;
        }
    }

    #pragma unroll
    for (int phase = 0; phase < TILE_H / 4; ++phase) {
        #pragma unroll
        for (int j = 0; j < 4; ++j) {
            const int step = phase * 4 + j;
            const int yr = by + 3 + step;            // newest row
            const int gy = reflect_idx(yr, HGT);
            const int idx = gy * WID + c0;
            float2 pa = *(const float2*)(p0 + idx);
            float2 ta = *(const float2*)(t0 + idx);
            float2 pb = *(const float2*)(p0 + HW + idx);
            float2 tb = *(const float2*)(t0 + HW + idx);
            float2 pc = *(const float2*)(p0 + 2*HW + idx);
            float2 tc = *(const float2*)(t0 + 2*HW + idx);
            float rx = fabsf(pa.x - ta.x) + fabsf(pb.x - tb.x) + fabsf(pc.x - tc.x);
            float ry = fabsf(pa.y - ta.y) + fabsf(pb.y - tb.y) + fabsf(pc.y - tc.y);
            if (yr < by + TILE_H) {                  // rows by+3..by+15
                s_acc  += rx + ry;
                ss_acc += rx*rx + ry*ry;
            }
            // 7-row window = ring[1..6] + new (incremental)
            float sx = sx_run + rx, qx = qx_run + rx * rx;
            float sy = sy_run + ry, qy = qy_run + ry * ry;
            *(float4*)&sV[j][c0] = make_float4(sx, qx, sy, qy);
            // shift ring, append new
            #pragma unroll
            for (int k = 0; k < 6; ++k) ring[k] = ring[k + 1];
            ring[6] = make_float2(rx, ry);
            centerR[j] = ring[3];                    // R at output row by+step
            // next running sums: window minus the row that leaves (ring[0])
            sx_run = sx - ring[0].x; qx_run = qx - ring[0].x * ring[0].x;
            sy_run = sy - ring[0].y; qy_run = qy - ring[0].y * ring[0].y;
        }
        __syncthreads();
        #pragma unroll
        for (int j = 0; j < 4; ++j) {
            // columns c0-3 .. c0+4 (8), reflect at image edges
            float cs[8], cq[8];
            #pragma unroll
            for (int k = 0; k < 8; ++k) {
                int cc = reflect_idx(c0 - 3 + k, WID);
                float2 v = sV[j][cc];
                cs[k] = v.x; cq[k] = v.y;
            }
            float s0 = 0.f, q0 = 0.f, s1 = 0.f, q1 = 0.f;
            #pragma unroll
            for (int k = 0; k < 7; ++k) {
                s0 += cs[k];     q0 += cq[k];
                s1 += cs[k + 1]; q1 += cq[k + 1];
            }
            float pw0 = (q0 - s0 * s0 * (1.0f/49.0f)) * (1.0f/48.0f);
            float pw1 = (q1 - s1 * s1 * (1.0f/49.0f)) * (1.0f/48.0f);
            wr_acc += pw0 * centerR[j].x + pw1 * centerR[j].y;
        }
        __syncthreads();
    }

    // Block reduce (8 warps) -> 3 double atomics.
    #pragma unroll
    for (int o = 16; o > 0; o >>= 1) {
        s_acc  += __shfl_down_sync(0xffffffffu, s_acc,  o);
        ss_acc += __shfl_down_sync(0xffffffffu, ss_acc, o);
        wr_acc += __shfl_down_sync(0xffffffffu, wr_acc, o);
    }
    const int lane = tid & 31, warp = tid >> 5;
    if (lane == 0) { red[0][warp] = s_acc; red[1][warp] = ss_acc; red[2][warp] = wr_acc; }
    __syncthreads();
    if (tid == 0) {
        float s = 0.f, ss = 0.f, wr = 0.f;
        #pragma unroll
        for (int w = 0; w < 8; ++w) { s += red[0][w]; ss += red[1][w]; wr += red[2][w]; }
        atomicAdd(&g_S[n],  (double)s);
        atomicAdd(&g_SS[n], (double)ss);
        atomicAdd(&g_WR[n], (double)wr);
        __threadfence();
        unsigned v = atomicAdd(&g_done, 1u);
        sLast = (v == NBLOCKS - 1);
    }
    __syncthreads();

    // Last block computes the loss (replaces the finalize launch).
    if (sLast && warp == 0) {
        __threadfence();
        const double M = (double)HW;
        double t = 0.0;
        if (lane < NB) {
            double S  = *(volatile double*)&g_S[lane];
            double SS = *(volatile double*)&g_SS[lane];
            double WR = *(volatile double*)&g_WR[lane];
            double var = (SS - S * S / M) / (M - 1.0);
            float  pw  = powf((float)var, 0.2f);
            t = (double)pw * WR;
            g_S[lane] = 0.0; g_SS[lane] = 0.0; g_WR[lane] = 0.0;  // reset for replay
        }
        #pragma unroll
        for (int o = 16; o > 0; o >>= 1)
            t += __shfl_down_sync(0xffffffffu, t, o);
        if (lane == 0) {
            out[0] = (float)(t / ((double)NB * CH * HW));
            g_done = 0;
        }
    }
}

extern "C" void kernel_launch(void* const* d_in, const int* in_sizes, int n_in,
                              void* d_out, int out_size)
{
    const float* pred = (const float*)d_in[0];
    const float* targ = (const float*)d_in[1];
    float* out = (float*)d_out;

    dim3 grid(1, HGT / TILE_H, NB);   // (1, 32, 16) = 512 blocks
    fused_kernel<<<grid, NTHR>>>(pred, targ, out);
}

// round 9
// speedup vs baseline: 1.0684x; 1.0684x over previous
#include <cuda_runtime.h>
#include <math.h>

#define NB 16
#define CH 3
#define HGT 512
#define WID 512
#define HW (HGT*WID)          // 262144

#define TILE_H 8
#define NTHR2  256
#define NBLOCKS2 (NB * (HGT / TILE_H))   // 1024

// Scratch residual (16 MB) + per-image accumulators + done counter.
// Zero-initialized at load; last pass-2 block resets accumulators/counter.
__device__ float    g_R[NB*HW];
__device__ double   g_S[NB];
__device__ double   g_SS[NB];
__device__ double   g_WR[NB];
__device__ unsigned g_done;

__device__ __forceinline__ int reflect_idx(int i, int n) {
    if (i < 0)  return -i;
    if (i >= n) return 2*n - 2 - i;
    return i;
}

// ---------------------------------------------------------------------------
// Pass 1: residual + per-image sum / sum-of-squares.
// 1 thread = 4 pixels (float4). 4096 blocks x 256 threads, fully parallel.
// ---------------------------------------------------------------------------
__global__ __launch_bounds__(256) void residual_kernel(
    const float* __restrict__ pred, const float* __restrict__ targ)
{
    const int gid = blockIdx.x * 256 + threadIdx.x;   // float4 index
    const int n   = gid / (HW/4);
    const int p4  = gid % (HW/4);

    const float4* pp = (const float4*)(pred + (size_t)n * CH * HW);
    const float4* tp = (const float4*)(targ + (size_t)n * CH * HW);

    float4 r = make_float4(0.f, 0.f, 0.f, 0.f);
    #pragma unroll
    for (int c = 0; c < CH; ++c) {
        float4 a = pp[c * (HW/4) + p4];
        float4 b = tp[c * (HW/4) + p4];
        r.x += fabsf(a.x - b.x);
        r.y += fabsf(a.y - b.y);
        r.z += fabsf(a.z - b.z);
        r.w += fabsf(a.w - b.w);
    }
    ((float4*)g_R)[(size_t)n * (HW/4) + p4] = r;

    float s  = r.x + r.y + r.z + r.w;
    float ss = r.x*r.x + r.y*r.y + r.z*r.z + r.w*r.w;

    #pragma unroll
    for (int o = 16; o > 0; o >>= 1) {
        s  += __shfl_down_sync(0xffffffffu, s,  o);
        ss += __shfl_down_sync(0xffffffffu, ss, o);
    }
    __shared__ float sh_s[8], sh_ss[8];
    const int lane = threadIdx.x & 31, wid = threadIdx.x >> 5;
    if (lane == 0) { sh_s[wid] = s; sh_ss[wid] = ss; }
    __syncthreads();
    if (wid == 0) {
        s  = (lane < 8) ? sh_s[lane]  : 0.f;
        ss = (lane < 8) ? sh_ss[lane] : 0.f;
        #pragma unroll
        for (int o = 4; o > 0; o >>= 1) {
            s  += __shfl_down_sync(0xffffffffu, s,  o);
            ss += __shfl_down_sync(0xffffffffu, ss, o);
        }
        if (lane == 0) {
            atomicAdd(&g_S[n],  (double)s);
            atomicAdd(&g_SS[n], (double)ss);
        }
    }
}

// ---------------------------------------------------------------------------
// Pass 2: 7x7 local unbiased variance over R (reflect) + WR accumulation
// + inline finalize in the last block.
// Block: 256 threads, thread t owns columns {2t, 2t+1} (float2 loads of R).
// Tile: full 512-wide x 8 rows. Grid: (1, 64, 16) = 1024 blocks.
// Per thread: only 14 float2 loads (ring of R rows), smem horizontal tap.
// ---------------------------------------------------------------------------
__global__ __launch_bounds__(NTHR2, 5) void localvar_kernel(float* __restrict__ out)
{
    const int n   = blockIdx.z;
    const int by  = blockIdx.y * TILE_H;
    const int tid = threadIdx.x;
    const int c0  = 2 * tid;

    __shared__ float2 sV[4][WID];      // vertical (sum, sumsq) per column
    __shared__ float  red[1][8];
    __shared__ int    sLast;

    const float* __restrict__ R = g_R + (size_t)n * HW;

    float2 ring[7];
    float2 centerR[4];
    float wr_acc = 0.f;

    #pragma unroll
    for (int k = 0; k < 6; ++k) {
        const int gy = reflect_idx(by - 3 + k, HGT);
        ring[k + 1] = *(const float2*)(R + gy * WID + c0);
    }

    #pragma unroll
    for (int phase = 0; phase < 2; ++phase) {
        #pragma unroll
        for (int j = 0; j < 4; ++j) {
            #pragma unroll
            for (int k = 0; k < 6; ++k) ring[k] = ring[k + 1];
            const int yr = by + 3 + phase * 4 + j;
            const int gy = reflect_idx(yr, HGT);
            ring[6] = *(const float2*)(R + gy * WID + c0);

            float sx = 0.f, sy = 0.f, qx = 0.f, qy = 0.f;
            #pragma unroll
            for (int k = 0; k < 7; ++k) {
                sx += ring[k].x; qx += ring[k].x * ring[k].x;
                sy += ring[k].y; qy += ring[k].y * ring[k].y;
            }
            *(float4*)&sV[j][c0] = make_float4(sx, qx, sy, qy);
            centerR[j] = ring[3];
        }
        __syncthreads();
        #pragma unroll
        for (int j = 0; j < 4; ++j) {
            float cs[8], cq[8];
            #pragma unroll
            for (int k = 0; k < 8; ++k) {
                int cc = reflect_idx(c0 - 3 + k, WID);
                float2 v = sV[j][cc];
                cs[k] = v.x; cq[k] = v.y;
            }
            float s0 = 0.f, q0 = 0.f, s1 = 0.f, q1 = 0.f;
            #pragma unroll
            for (int k = 0; k < 7; ++k) {
                s0 += cs[k];     q0 += cq[k];
                s1 += cs[k + 1]; q1 += cq[k + 1];
            }
            float pw0 = (q0 - s0 * s0 * (1.0f/49.0f)) * (1.0f/48.0f);
            float pw1 = (q1 - s1 * s1 * (1.0f/49.0f)) * (1.0f/48.0f);
            wr_acc += pw0 * centerR[j].x + pw1 * centerR[j].y;
        }
        __syncthreads();
    }

    #pragma unroll
    for (int o = 16; o > 0; o >>= 1)
        wr_acc += __shfl_down_sync(0xffffffffu, wr_acc, o);
    const int lane = tid & 31, warp = tid >> 5;
    if (lane == 0) red[0][warp] = wr_acc;
    __syncthreads();
    if (tid == 0) {
        float wr = 0.f;
        #pragma unroll
        for (int w = 0; w < 8; ++w) wr += red[0][w];
        atomicAdd(&g_WR[n], (double)wr);
        __threadfence();
        unsigned v = atomicAdd(&g_done, 1u);
        sLast = (v == NBLOCKS2 - 1);
    }
    __syncthreads();

    if (sLast && warp == 0) {
        __threadfence();
        const double M = (double)HW;
        double t = 0.0;
        if (lane < NB) {
            double S  = *(volatile double*)&g_S[lane];
            double SS = *(volatile double*)&g_SS[lane];
            double WR = *(volatile double*)&g_WR[lane];
            double var = (SS - S * S / M) / (M - 1.0);
            float  pw  = powf((float)var, 0.2f);
            t = (double)pw * WR;
            g_S[lane] = 0.0; g_SS[lane] = 0.0; g_WR[lane] = 0.0;
        }
        #pragma unroll
        for (int o = 16; o > 0; o >>= 1)
            t += __shfl_down_sync(0xffffffffu, t, o);
        if (lane == 0) {
            out[0] = (float)(t / ((double)NB * CH * HW));
            g_done = 0;
        }
    }
}

extern "C" void kernel_launch(void* const* d_in, const int* in_sizes, int n_in,
                              void* d_out, int out_size)
{
    const float* pred = (const float*)d_in[0];
    const float* targ = (const float*)d_in[1];
    float* out = (float*)d_out;

    residual_kernel<<<(NB*HW/4) / 256, 256>>>(pred, targ);
    dim3 grid2(1, HGT / TILE_H, NB);   // 1024 blocks
    localvar_kernel<<<grid2, NTHR2>>>(out);
}

// round 10
// speedup vs baseline: 1.7128x; 1.6032x over previous
#include <cuda_runtime.h>
#include <math.h>

#define NB 16
#define CH 3
#define HGT 512
#define WID 512
#define HW (HGT*WID)          // 262144

#define TILE_H 8
#define NTHR   128            // 4 columns per thread (float4) -> 512-wide rows
#define NBLOCKS (NB * (HGT / TILE_H))   // 1024

// Per-image accumulators + completion counter. Zero-initialized at load;
// the last block resets everything so each graph replay starts clean.
__device__ double   g_S[NB];
__device__ double   g_SS[NB];
__device__ double   g_WR[NB];
__device__ unsigned g_done;

__device__ __forceinline__ int reflect_idx(int i, int n) {
    if (i < 0)  return -i;
    if (i >= n) return 2*n - 2 - i;
    return i;
}

// ---------------------------------------------------------------------------
// Fully fused: residual on-the-fly + 7x7 local unbiased variance (reflect)
// + per-image S/SS/WR accumulation + final loss (last block).
// Block: 128 threads; thread t owns columns 4t..4t+3 (float4 loads).
// Tile: full 512-wide x 8 rows. Grid: (1, 64, 16) = 1024 blocks ->
// with 8 blocks/SM all resident in a single wave (148*8 = 1184 >= 1024).
// Vertical 7-window: float4 register ring. Horizontal 7-tap: padded smem,
// aligned float4 reads, incremental sliding windows.
// ---------------------------------------------------------------------------
__global__ __launch_bounds__(NTHR, 8) void fused_kernel(
    const float* __restrict__ pred, const float* __restrict__ targ,
    float* __restrict__ out)
{
    const int n   = blockIdx.z;
    const int by  = blockIdx.y * TILE_H;
    const int tid = threadIdx.x;
    const int c0  = 4 * tid;

    // +4 left pad, +4 right pad (only 3 of each used) for reflected columns.
    __shared__ float sVs[4][WID + 8];
    __shared__ float sVq[4][WID + 8];
    __shared__ float red[4];
    __shared__ int   sLast;

    const float* __restrict__ p0 = pred + (size_t)n * CH * HW;
    const float* __restrict__ t0 = targ + (size_t)n * CH * HW;

    float4 ring[7];
    float4 centerR[4];
    float s_acc = 0.f, ss_acc = 0.f, wr_acc = 0.f;

    // Prefill ring slots 1..6 with logical rows by-3 .. by+2.
    #pragma unroll
    for (int k = 0; k < 6; ++k) {
        const int yr = by - 3 + k;
        const int gy = reflect_idx(yr, HGT);
        const int idx = gy * WID + c0;
        float4 pa = *(const float4*)(p0 + idx);
        float4 ta = *(const float4*)(t0 + idx);
        float4 pb = *(const float4*)(p0 + HW + idx);
        float4 tb = *(const float4*)(t0 + HW + idx);
        float4 pc = *(const float4*)(p0 + 2*HW + idx);
        float4 tc = *(const float4*)(t0 + 2*HW + idx);
        float4 r;
        r.x = fabsf(pa.x - ta.x) + fabsf(pb.x - tb.x) + fabsf(pc.x - tc.x);
        r.y = fabsf(pa.y - ta.y) + fabsf(pb.y - tb.y) + fabsf(pc.y - tc.y);
        r.z = fabsf(pa.z - ta.z) + fabsf(pb.z - tb.z) + fabsf(pc.z - tc.z);
        r.w = fabsf(pa.w - ta.w) + fabsf(pb.w - tb.w) + fabsf(pc.w - tc.w);
        ring[k + 1] = r;
        if (k >= 3) {                     // rows by..by+2: count once
            s_acc  += r.x + r.y + r.z + r.w;
            ss_acc += r.x*r.x + r.y*r.y + r.z*r.z + r.w*r.w;
        }
    }

    #pragma unroll
    for (int phase = 0; phase < 2; ++phase) {
        #pragma unroll
        for (int j = 0; j < 4; ++j) {
            #pragma unroll
            for (int k = 0; k < 6; ++k) ring[k] = ring[k + 1];
            const int yr = by + 3 + phase * 4 + j;   // newest row
            const int gy = reflect_idx(yr, HGT);
            const int idx = gy * WID + c0;
            float4 pa = *(const float4*)(p0 + idx);
            float4 ta = *(const float4*)(t0 + idx);
            float4 pb = *(const float4*)(p0 + HW + idx);
            float4 tb = *(const float4*)(t0 + HW + idx);
            float4 pc = *(const float4*)(p0 + 2*HW + idx);
            float4 tc = *(const float4*)(t0 + 2*HW + idx);
            float4 r;
            r.x = fabsf(pa.x - ta.x) + fabsf(pb.x - tb.x) + fabsf(pc.x - tc.x);
            r.y = fabsf(pa.y - ta.y) + fabsf(pb.y - tb.y) + fabsf(pc.y - tc.y);
            r.z = fabsf(pa.z - ta.z) + fabsf(pb.z - tb.z) + fabsf(pc.z - tc.z);
            r.w = fabsf(pa.w - ta.w) + fabsf(pb.w - tb.w) + fabsf(pc.w - tc.w);
            ring[6] = r;
            if (yr < by + TILE_H) {                  // rows by+3..by+7
                s_acc  += r.x + r.y + r.z + r.w;
                ss_acc += r.x*r.x + r.y*r.y + r.z*r.z + r.w*r.w;
            }
            float4 s4 = make_float4(0.f, 0.f, 0.f, 0.f);
            float4 q4 = make_float4(0.f, 0.f, 0.f, 0.f);
            #pragma unroll
            for (int k = 0; k < 7; ++k) {
                float4 v = ring[k];
                s4.x += v.x; q4.x += v.x * v.x;
                s4.y += v.y; q4.y += v.y * v.y;
                s4.z += v.z; q4.z += v.z * v.z;
                s4.w += v.w; q4.w += v.w * v.w;
            }
            *(float4*)&sVs[j][4 + c0] = s4;
            *(float4*)&sVq[j][4 + c0] = q4;
            // reflected column pads: left cols -3..-1 = cols 3,2,1;
            // right cols 512..514 = cols 510,509,508.
            if (tid == 0) {
                sVs[j][1] = s4.w; sVs[j][2] = s4.z; sVs[j][3] = s4.y;
                sVq[j][1] = q4.w; sVq[j][2] = q4.z; sVq[j][3] = q4.y;
            }
            if (tid == NTHR - 1) {
                sVs[j][4 + 512] = s4.z; sVs[j][5 + 512] = s4.y; sVs[j][6 + 512] = s4.x;
                sVq[j][4 + 512] = q4.z; sVq[j][5 + 512] = q4.y; sVq[j][6 + 512] = q4.x;
            }
            centerR[j] = ring[3];                    // R at output row
        }
        __syncthreads();
        #pragma unroll
        for (int j = 0; j < 4; ++j) {
            // columns c0-4 .. c0+7 via three aligned float4 reads (pad offset 4)
            float4 a0 = *(const float4*)&sVs[j][c0];
            float4 a1 = *(const float4*)&sVs[j][c0 + 4];
            float4 a2 = *(const float4*)&sVs[j][c0 + 8];
            float4 b0 = *(const float4*)&sVq[j][c0];
            float4 b1 = *(const float4*)&sVq[j][c0 + 4];
            float4 b2 = *(const float4*)&sVq[j][c0 + 8];
            // cs[0..11] = cols c0-4 .. c0+7 ; windows need cs[1..10]
            float s0 = a0.y + a0.z + a0.w + a1.x + a1.y + a1.z + a1.w;
            float q0 = b0.y + b0.z + b0.w + b1.x + b1.y + b1.z + b1.w;
            float s1 = s0 - a0.y + a2.x;
            float q1 = q0 - b0.y + b2.x;
            float s2 = s1 - a0.z + a2.y;
            float q2 = q1 - b0.z + b2.y;
            float s3 = s2 - a0.w + a2.z;
            float q3 = q2 - b0.w + b2.z;
            float pw0 = (q0 - s0 * s0 * (1.0f/49.0f)) * (1.0f/48.0f);
            float pw1 = (q1 - s1 * s1 * (1.0f/49.0f)) * (1.0f/48.0f);
            float pw2 = (q2 - s2 * s2 * (1.0f/49.0f)) * (1.0f/48.0f);
            float pw3 = (q3 - s3 * s3 * (1.0f/49.0f)) * (1.0f/48.0f);
            wr_acc += pw0 * centerR[j].x + pw1 * centerR[j].y
                    + pw2 * centerR[j].z + pw3 * centerR[j].w;
        }
        __syncthreads();
    }

    // Block reduce (4 warps) -> 3 double atomics.
    #pragma unroll
    for (int o = 16; o > 0; o >>= 1) {
        s_acc  += __shfl_down_sync(0xffffffffu, s_acc,  o);
        ss_acc += __shfl_down_sync(0xffffffffu, ss_acc, o);
        wr_acc += __shfl_down_sync(0xffffffffu, wr_acc, o);
    }
    const int lane = tid & 31, warp = tid >> 5;
    // reuse sVs row 0 as scratch for the 3 partial sums per warp
    if (lane == 0) {
        sVs[0][warp] = s_acc; sVs[0][8 + warp] = ss_acc; sVs[0][16 + warp] = wr_acc;
    }
    __syncthreads();
    if (tid == 0) {
        float s = 0.f, ss = 0.f, wr = 0.f;
        #pragma unroll
        for (int w = 0; w < 4; ++w) {
            s += sVs[0][w]; ss += sVs[0][8 + w]; wr += sVs[0][16 + w];
        }
        atomicAdd(&g_S[n],  (double)s);
        atomicAdd(&g_SS[n], (double)ss);
        atomicAdd(&g_WR[n], (double)wr);
        __threadfence();
        unsigned v = atomicAdd(&g_done, 1u);
        sLast = (v == NBLOCKS - 1);
    }
    __syncthreads();

    // Last block computes the loss (no separate finalize launch).
    if (sLast && warp == 0) {
        __threadfence();
        const double M = (double)HW;
        double t = 0.0;
        if (lane < NB) {
            double S  = *(volatile double*)&g_S[lane];
            double SS = *(volatile double*)&g_SS[lane];
            double WR = *(volatile double*)&g_WR[lane];
            double var = (SS - S * S / M) / (M - 1.0);
            float  pw  = powf((float)var, 0.2f);
            t = (double)pw * WR;
            g_S[lane] = 0.0; g_SS[lane] = 0.0; g_WR[lane] = 0.0;  // reset for replay
        }
        #pragma unroll
        for (int o = 16; o > 0; o >>= 1)
            t += __shfl_down_sync(0xffffffffu, t, o);
        if (lane == 0) {
            out[0] = (float)(t / ((double)NB * CH * HW));
            g_done = 0;
        }
    }
}

extern "C" void kernel_launch(void* const* d_in, const int* in_sizes, int n_in,
                              void* d_out, int out_size)
{
    const float* pred = (const float*)d_in[0];
    const float* targ = (const float*)d_in[1];
    float* out = (float*)d_out;

    dim3 grid(1, HGT / TILE_H, NB);   // (1, 64, 16) = 1024 blocks
    fused_kernel<<<grid, NTHR>>>(pred, targ, out);
}